// round 14
// baseline (speedup 1.0000x reference)
#include <cuda_runtime.h>

#define FULL 0xFFFFFFFFu
#define MAX_DEG 64
#define MAXN 10240
#define DEPTH 3            // ring slots per warp
#define CHUNK_F4 256       // float4 per chunk (4KB)
#define CHUNK_BYTES 4096

// ---------------- scratch (no allocations allowed) ----------------
__device__ int    g_nbr[MAXN * MAX_DEG];
__device__ int    g_deg[MAXN];
__device__ float  g_Wh01[MAXN * 16];     // cols 0-7 head0, 8-15 head1
__device__ float2 g_fs01[MAXN];          // (fs0, fs1)
__device__ float2 g_fd01[MAXN];          // (fd0, fd1)
__device__ float  g_Who[MAXN * 16];
__device__ float  g_fso[MAXN], g_fdo[MAXN];
__device__ float  g_ns[MAXN];            // per-node pred score

// ---- smem helpers ----
__device__ __forceinline__ unsigned smem_u32(const void* p) {
    return (unsigned)__cvta_generic_to_shared(p);
}
__device__ __forceinline__ void mbar_init(unsigned mbar) {
    asm volatile("mbarrier.init.shared.b64 [%0], %1;" :: "r"(mbar), "r"(1) : "memory");
}
__device__ __forceinline__ void bulk_issue(unsigned dst, const char* src,
                                           unsigned bytes, unsigned mbar) {
    asm volatile("mbarrier.arrive.expect_tx.shared.b64 _, [%0], %1;"
                 :: "r"(mbar), "r"(bytes) : "memory");
    asm volatile("cp.async.bulk.shared::cluster.global.mbarrier::complete_tx::bytes "
                 "[%0], [%1], %2, [%3];"
                 :: "r"(dst), "l"(src), "r"(bytes), "r"(mbar) : "memory");
}
__device__ __forceinline__ void mbar_wait(unsigned mbar, unsigned parity) {
    asm volatile(
        "{\n\t.reg .pred P;\n\t"
        "WAIT_%=:\n\t"
        "mbarrier.try_wait.parity.acquire.cta.shared::cta.b64 P, [%0], %1, 0x989680;\n\t"
        "@P bra.uni DONE_%=;\n\t"
        "bra.uni WAIT_%=;\n\t"
        "DONE_%=:\n\t}"
        :: "r"(mbar), "r"(parity) : "memory");
}

// ============ kernel 1: features + hidden-head Wh / attn coefficients ========
__global__ void k_feat_wh(
    const int* __restrict__ all_gender, const int* __restrict__ all_age,
    const int* __restrict__ all_job, const int* __restrict__ all_mtype,
    const float* __restrict__ E_uid, const float* __restrict__ E_gender,
    const float* __restrict__ E_age, const float* __restrict__ E_job,
    const float* __restrict__ E_mid, const float* __restrict__ E_mtype,
    const float* __restrict__ Wu, const float* __restrict__ bu,
    const float* __restrict__ Wm, const float* __restrict__ bm,
    const float* __restrict__ W0, const float* __restrict__ a0,
    const float* __restrict__ W1, const float* __restrict__ a1,
    int U, int N)
{
    int t = blockIdx.x * blockDim.x + threadIdx.x;
    int i = t >> 5;
    int lane = threadIdx.x & 31;
    if (i >= N) return;
    int c = lane;
    float x;
    if (i < U) {
        x = bu[c];
        const float* eu = E_uid + (size_t)i * 32;
#pragma unroll
        for (int k = 0; k < 32; k++) x += eu[k] * Wu[k * 32 + c];
        const float* eg = E_gender + all_gender[i] * 16;
#pragma unroll
        for (int k = 0; k < 16; k++) x += eg[k] * Wu[(32 + k) * 32 + c];
        const float* ea = E_age + all_age[i] * 16;
#pragma unroll
        for (int k = 0; k < 16; k++) x += ea[k] * Wu[(48 + k) * 32 + c];
        const float* ej = E_job + all_job[i] * 16;
#pragma unroll
        for (int k = 0; k < 16; k++) x += ej[k] * Wu[(64 + k) * 32 + c];
    } else {
        int m = i - U;
        x = bm[c];
        const float* em = E_mid + (size_t)m * 32;
#pragma unroll
        for (int k = 0; k < 32; k++) x += em[k] * Wm[k * 32 + c];
        int t0 = all_mtype[m * 3 + 0];
        int t1 = all_mtype[m * 3 + 1];
        int t2 = all_mtype[m * 3 + 2];
        const float* e0 = E_mtype + t0 * 32;
        const float* e1 = E_mtype + t1 * 32;
        const float* e2 = E_mtype + t2 * 32;
#pragma unroll
        for (int k = 0; k < 32; k++)
            x += (e0[k] + e1[k] + e2[k]) * Wm[(32 + k) * 32 + c];
    }
    int c8 = lane & 7;
    const float* W = (lane < 8) ? W0 : W1;
    const float* a = (lane < 8) ? a0 : a1;
    float wv = 0.f;
#pragma unroll
    for (int k = 0; k < 32; k++) {
        float xk = __shfl_sync(FULL, x, k);
        wv += xk * W[k * 8 + c8];
    }
    if (lane < 16) g_Wh01[i * 16 + lane] = wv;
    float ts = wv * a[c8];
    float td = wv * a[8 + c8];
#pragma unroll
    for (int o = 4; o; o >>= 1) {
        ts += __shfl_xor_sync(FULL, ts, o);
        td += __shfl_xor_sync(FULL, td, o);
    }
    float fs1v = __shfl_sync(FULL, ts, 8);
    float fd1v = __shfl_sync(FULL, td, 8);
    if (lane == 0) {
        g_fs01[i] = make_float2(ts, fs1v);
        g_fd01[i] = make_float2(td, fd1v);
    }
}

// ============ kernel 2: TMA-bulk CSR build + hidden attention + W_out map ====
// warp per row. Phase A: per-warp private ring of DEPTH x 4KB chunks filled by
// cp.async.bulk + mbarrier (lane 0 produces, all lanes consume). Phase B:
// 2-head sparse softmax + gather + ELU + fused output-head linear.
__global__ void __launch_bounds__(256) k_csr_attn(
    const float* __restrict__ adj, const float* __restrict__ Wo,
    const float* __restrict__ ao, int N)
{
    extern __shared__ float4 ring[];                  // [8][DEPTH*CHUNK_F4]
    __shared__ __align__(8) unsigned long long mbar_s[8][DEPTH];
    __shared__ int    nb_s[8][MAX_DEG];
    __shared__ float4 pack[8][MAX_DEG];
    int w = (blockIdx.x * blockDim.x + threadIdx.x) >> 5;
    int wl = threadIdx.x >> 5;
    int lane = threadIdx.x & 31;
    if (w >= N) return;

    unsigned ring_base = smem_u32(ring) + wl * (DEPTH * CHUNK_BYTES);
    unsigned mb[DEPTH];
#pragma unroll
    for (int s = 0; s < DEPTH; s++) mb[s] = smem_u32(&mbar_s[wl][s]);
    if (lane == 0) {
#pragma unroll
        for (int s = 0; s < DEPTH; s++) mbar_init(mb[s]);
    }
    __syncwarp();

    // ---- Phase A: bulk stream + compact ----
    const char* rowb = reinterpret_cast<const char*>(adj + (size_t)w * N);
    int n4 = N >> 2;
    int nchunks = (n4 + CHUNK_F4 - 1) / CHUNK_F4;
    int base = 0;

    int pro = DEPTH < nchunks ? DEPTH : nchunks;
    if (lane == 0) {
        for (int p = 0; p < pro; p++) {
            int f4s = n4 - p * CHUNK_F4;
            if (f4s > CHUNK_F4) f4s = CHUNK_F4;
            bulk_issue(ring_base + p * CHUNK_BYTES,
                       rowb + (size_t)p * CHUNK_BYTES, f4s * 16, mb[p]);
        }
    }

    for (int c = 0; c < nchunks; c++) {
        int slot = c % DEPTH;
        unsigned parity = (unsigned)((c / DEPTH) & 1);
        mbar_wait(mb[slot], parity);
        const float4* sp = reinterpret_cast<const float4*>(ring) +
                           (wl * DEPTH + slot) * CHUNK_F4;
        int cbase = c * CHUNK_F4;
        float4 v[8];
#pragma unroll
        for (int k = 0; k < 8; k++) {
            int f4i = cbase + k * 32 + lane;
            v[k] = make_float4(0.f, 0.f, 0.f, 0.f);
            if (f4i < n4) v[k] = sp[k * 32 + lane];
        }
        int fl[32];
#pragma unroll
        for (int k = 0; k < 8; k++) {
            fl[k * 4 + 0] = v[k].x > 0.f;
            fl[k * 4 + 1] = v[k].y > 0.f;
            fl[k * 4 + 2] = v[k].z > 0.f;
            fl[k * 4 + 3] = v[k].w > 0.f;
        }
        int cnt = 0;
#pragma unroll
        for (int e = 0; e < 32; e++) cnt += fl[e];
        int s = cnt;
#pragma unroll
        for (int off = 1; off < 32; off <<= 1) {
            int u = __shfl_up_sync(FULL, s, off);
            if (lane >= off) s += u;
        }
        int pos = base + (s - cnt);
#pragma unroll
        for (int k = 0; k < 8; k++) {
            int cb = (cbase + k * 32 + lane) * 4;
#pragma unroll
            for (int e = 0; e < 4; e++) {
                if (fl[k * 4 + e]) {
                    if (pos < MAX_DEG) nb_s[wl][pos] = cb + e;
                    pos++;
                }
            }
        }
        base += __shfl_sync(FULL, s, 31);
        __syncwarp();
        // refill this slot for chunk c+DEPTH
        int nc = c + DEPTH;
        if (nc < nchunks && lane == 0) {
            int f4s = n4 - nc * CHUNK_F4;
            if (f4s > CHUNK_F4) f4s = CHUNK_F4;
            bulk_issue(ring_base + slot * CHUNK_BYTES,
                       rowb + (size_t)nc * CHUNK_BYTES, f4s * 16, mb[slot]);
        }
    }
    int rem = N & 3;
    if (rem) {
        int colbase = N & ~3;
        int flag = 0;
        if (lane < rem) flag = adj[(size_t)w * N + colbase + lane] > 0.f;
        int s = flag;
#pragma unroll
        for (int off = 1; off < 32; off <<= 1) {
            int u = __shfl_up_sync(FULL, s, off);
            if (lane >= off) s += u;
        }
        if (flag) {
            int pos = base + s - 1;
            if (pos < MAX_DEG) nb_s[wl][pos] = colbase + lane;
        }
        base += __shfl_sync(FULL, s, 31);
    }
    int deg = base < MAX_DEG ? base : MAX_DEG;
    __syncwarp();
    if (lane < deg) g_nbr[(size_t)w * MAX_DEG + lane] = nb_s[wl][lane];
    if (lane + 32 < deg) g_nbr[(size_t)w * MAX_DEG + lane + 32] = nb_s[wl][lane + 32];
    if (lane == 0) g_deg[w] = deg;

    // ---- Phase B: hidden 2-head attention ----
    float2 fsi = g_fs01[w];
    int j1 = (lane < deg) ? nb_s[wl][lane] : -1;
    int j2 = (lane + 32 < deg) ? nb_s[wl][lane + 32] : -1;
    float w01 = 0.f, w02 = 0.f, w11 = 0.f, w12 = 0.f;
    if (j1 >= 0) {
        float2 fd = g_fd01[j1];
        float a = fsi.x + fd.x; a = (a > 0.f) ? a : 0.2f * a; w01 = __expf(a);
        float b = fsi.y + fd.y; b = (b > 0.f) ? b : 0.2f * b; w11 = __expf(b);
    }
    if (j2 >= 0) {
        float2 fd = g_fd01[j2];
        float a = fsi.x + fd.x; a = (a > 0.f) ? a : 0.2f * a; w02 = __expf(a);
        float b = fsi.y + fd.y; b = (b > 0.f) ? b : 0.2f * b; w12 = __expf(b);
    }
    float s0 = w01 + w02, s1 = w11 + w12;
#pragma unroll
    for (int o = 16; o; o >>= 1) {
        s0 += __shfl_xor_sync(FULL, s0, o);
        s1 += __shfl_xor_sync(FULL, s1, o);
    }
    float inv0 = 1.f / s0, inv1 = 1.f / s1;
    pack[wl][lane]      = make_float4(__int_as_float(j1), w01 * inv0, w11 * inv1, 0.f);
    pack[wl][lane + 32] = make_float4(__int_as_float(j2), w02 * inv0, w12 * inv1, 0.f);
    __syncwarp();
    int half = lane >> 4, c = lane & 15;
    float acc = 0.f, acc2 = 0.f;
    int n = half;
    for (; n + 2 < deg; n += 4) {
        float4 va = pack[wl][n];
        float4 vb = pack[wl][n + 2];
        int ja = __float_as_int(va.x);
        int jb = __float_as_int(vb.x);
        acc  += ((c < 8) ? va.y : va.z) * g_Wh01[ja * 16 + c];
        acc2 += ((c < 8) ? vb.y : vb.z) * g_Wh01[jb * 16 + c];
    }
    for (; n < deg; n += 2) {
        float4 va = pack[wl][n];
        int ja = __float_as_int(va.x);
        acc += ((c < 8) ? va.y : va.z) * g_Wh01[ja * 16 + c];
    }
    acc += acc2;
    acc += __shfl_xor_sync(FULL, acc, 16);
    float h = (acc > 0.f) ? acc : (expf(acc) - 1.f);   // ELU on concat heads
    float who = 0.f;
#pragma unroll
    for (int k = 0; k < 16; k++) {
        float hk = __shfl_sync(FULL, h, k);
        who += hk * Wo[k * 16 + c];
    }
    float fs = who * ao[c];
    float fd = who * ao[16 + c];
#pragma unroll
    for (int o = 8; o; o >>= 1) {
        fs += __shfl_xor_sync(FULL, fs, o);
        fd += __shfl_xor_sync(FULL, fd, o);
    }
    if (half == 0) g_Who[w * 16 + c] = who;
    if (lane == 0) { g_fso[w] = fs; g_fdo[w] = fd; }
}

// ============ kernel 3: output attention head + fused per-node pred score ====
__global__ void k_attn_out(const float* __restrict__ Wp, int U, int N)
{
    __shared__ float2 sm[8][MAX_DEG];
    int w = (blockIdx.x * blockDim.x + threadIdx.x) >> 5;
    int wl = threadIdx.x >> 5;
    int lane = threadIdx.x & 31;
    if (w >= N) return;
    int deg = g_deg[w];
    const int* nb = g_nbr + (size_t)w * MAX_DEG;
    int j1 = (lane < deg) ? nb[lane] : -1;
    int j2 = (lane + 32 < deg) ? nb[lane + 32] : -1;
    float fsi = g_fso[w];
    float w1 = 0.f, w2 = 0.f;
    if (j1 >= 0) { float a = fsi + g_fdo[j1]; a = (a > 0.f) ? a : 0.2f * a; w1 = __expf(a); }
    if (j2 >= 0) { float a = fsi + g_fdo[j2]; a = (a > 0.f) ? a : 0.2f * a; w2 = __expf(a); }
    float s = w1 + w2;
#pragma unroll
    for (int o = 16; o; o >>= 1) s += __shfl_xor_sync(FULL, s, o);
    float inv = 1.f / s;
    sm[wl][lane]      = make_float2(__int_as_float(j1), w1 * inv);
    sm[wl][lane + 32] = make_float2(__int_as_float(j2), w2 * inv);
    __syncwarp();
    int half = lane >> 4, c = lane & 15;
    float a0 = 0.f, a1 = 0.f, a2 = 0.f, a3 = 0.f;
    int n = half;
    for (; n + 6 < deg; n += 8) {
        float2 v0 = sm[wl][n];
        float2 v1 = sm[wl][n + 2];
        float2 v2 = sm[wl][n + 4];
        float2 v3 = sm[wl][n + 6];
        a0 += v0.y * g_Who[__float_as_int(v0.x) * 16 + c];
        a1 += v1.y * g_Who[__float_as_int(v1.x) * 16 + c];
        a2 += v2.y * g_Who[__float_as_int(v2.x) * 16 + c];
        a3 += v3.y * g_Who[__float_as_int(v3.x) * 16 + c];
    }
    for (; n < deg; n += 2) {
        float2 v0 = sm[wl][n];
        a0 += v0.y * g_Who[__float_as_int(v0.x) * 16 + c];
    }
    float acc = (a0 + a1) + (a2 + a3);
    acc += __shfl_xor_sync(FULL, acc, 16);
    float g = (acc > 0.f) ? acc : (expf(acc) - 1.f);   // outer ELU
    float ps = g * Wp[(w < U ? 0 : 16) + c];
#pragma unroll
    for (int o = 8; o; o >>= 1) ps += __shfl_xor_sync(FULL, ps, o);
    if (lane == 0) g_ns[w] = ps;
}

// ============ kernel 4: prediction head (2 scalar loads + sigmoid) ===========
__global__ void k_pred(const int* __restrict__ uid, const int* __restrict__ mid,
                       const float* __restrict__ bp,
                       float* __restrict__ out, int B, int U, int write_rating)
{
    int b = blockIdx.x * blockDim.x + threadIdx.x;
    if (b >= B) return;
    float acc = g_ns[uid[b]] + g_ns[mid[b] + U] + bp[0];
    float p = 5.f / (1.f + expf(-acc));
    out[b] = p;
    if (write_rating) out[B + b] = ceilf(p);
}

// ---------------- launch ----------------
extern "C" void kernel_launch(void* const* d_in, const int* in_sizes, int n_in,
                              void* d_out, int out_size)
{
    const int*   uid        = (const int*)d_in[0];
    const int*   mid        = (const int*)d_in[1];
    const int*   all_gender = (const int*)d_in[2];
    const int*   all_age    = (const int*)d_in[3];
    const int*   all_job    = (const int*)d_in[4];
    const int*   all_mtype  = (const int*)d_in[5];
    const float* adj        = (const float*)d_in[6];
    const float* E_uid      = (const float*)d_in[7];
    const float* E_gender   = (const float*)d_in[8];
    const float* E_age      = (const float*)d_in[9];
    const float* E_job      = (const float*)d_in[10];
    const float* E_mid      = (const float*)d_in[11];
    const float* E_mtype    = (const float*)d_in[12];
    const float* W_user_map = (const float*)d_in[13];
    const float* b_user_map = (const float*)d_in[14];
    const float* W_movie    = (const float*)d_in[15];
    const float* b_movie    = (const float*)d_in[16];
    const float* W_h0       = (const float*)d_in[17];
    const float* a_h0       = (const float*)d_in[18];
    const float* W_h1       = (const float*)d_in[19];
    const float* a_h1       = (const float*)d_in[20];
    const float* W_out      = (const float*)d_in[21];
    const float* a_out      = (const float*)d_in[22];
    const float* W_pred     = (const float*)d_in[23];
    const float* b_pred     = (const float*)d_in[24];

    int B = in_sizes[0];
    int U = in_sizes[2];
    int M = in_sizes[5] / 3;
    int N = U + M;
    float* out = (float*)d_out;
    int write_rating = (out_size >= 2 * B) ? 1 : 0;

    const int RING_BYTES = 8 * DEPTH * CHUNK_BYTES;   // 96KB dynamic smem
    static bool inited = false;
    if (!inited) {
        cudaFuncSetAttribute(k_csr_attn,
                             cudaFuncAttributeMaxDynamicSharedMemorySize, RING_BYTES);
        inited = true;
    }

    int tpw = N * 32;
    k_feat_wh<<<(tpw + 255) / 256, 256>>>(
        all_gender, all_age, all_job, all_mtype,
        E_uid, E_gender, E_age, E_job, E_mid, E_mtype,
        W_user_map, b_user_map, W_movie, b_movie,
        W_h0, a_h0, W_h1, a_h1, U, N);
    k_csr_attn<<<(tpw + 255) / 256, 256, RING_BYTES>>>(adj, W_out, a_out, N);
    k_attn_out<<<(tpw + 255) / 256, 256>>>(W_pred, U, N);
    k_pred<<<(B + 255) / 256, 256>>>(uid, mid, b_pred, out, B, U, write_rating);
}

// round 15
// speedup vs baseline: 1.1991x; 1.1991x over previous
#include <cuda_runtime.h>

#define FULL 0xFFFFFFFFu
#define MAX_DEG 64
#define MAXN 10240

// ---------------- scratch (no allocations allowed) ----------------
__device__ int    g_nbr[MAXN * MAX_DEG];
__device__ int    g_deg[MAXN];
__device__ float  g_Wh01[MAXN * 16];     // cols 0-7 head0, 8-15 head1
__device__ float2 g_fs01[MAXN];          // (fs0, fs1)
__device__ float2 g_fd01[MAXN];          // (fd0, fd1)
__device__ float  g_Who[MAXN * 16];
__device__ float  g_fso[MAXN], g_fdo[MAXN];
__device__ float  g_gcn[MAXN * 16];

// ============ kernel 1: features + hidden-head Wh / attn coefficients ========
__global__ void k_feat_wh(
    const int* __restrict__ all_gender, const int* __restrict__ all_age,
    const int* __restrict__ all_job, const int* __restrict__ all_mtype,
    const float* __restrict__ E_uid, const float* __restrict__ E_gender,
    const float* __restrict__ E_age, const float* __restrict__ E_job,
    const float* __restrict__ E_mid, const float* __restrict__ E_mtype,
    const float* __restrict__ Wu, const float* __restrict__ bu,
    const float* __restrict__ Wm, const float* __restrict__ bm,
    const float* __restrict__ W0, const float* __restrict__ a0,
    const float* __restrict__ W1, const float* __restrict__ a1,
    int U, int N)
{
    int t = blockIdx.x * blockDim.x + threadIdx.x;
    int i = t >> 5;
    int lane = threadIdx.x & 31;
    if (i >= N) return;
    int c = lane;
    float x;
    if (i < U) {
        x = bu[c];
        const float* eu = E_uid + (size_t)i * 32;
#pragma unroll
        for (int k = 0; k < 32; k++) x += eu[k] * Wu[k * 32 + c];
        const float* eg = E_gender + all_gender[i] * 16;
#pragma unroll
        for (int k = 0; k < 16; k++) x += eg[k] * Wu[(32 + k) * 32 + c];
        const float* ea = E_age + all_age[i] * 16;
#pragma unroll
        for (int k = 0; k < 16; k++) x += ea[k] * Wu[(48 + k) * 32 + c];
        const float* ej = E_job + all_job[i] * 16;
#pragma unroll
        for (int k = 0; k < 16; k++) x += ej[k] * Wu[(64 + k) * 32 + c];
    } else {
        int m = i - U;
        x = bm[c];
        const float* em = E_mid + (size_t)m * 32;
#pragma unroll
        for (int k = 0; k < 32; k++) x += em[k] * Wm[k * 32 + c];
        int t0 = all_mtype[m * 3 + 0];
        int t1 = all_mtype[m * 3 + 1];
        int t2 = all_mtype[m * 3 + 2];
        const float* e0 = E_mtype + t0 * 32;
        const float* e1 = E_mtype + t1 * 32;
        const float* e2 = E_mtype + t2 * 32;
#pragma unroll
        for (int k = 0; k < 32; k++) {
            float s = e0[k] + e1[k] + e2[k];
            x += s * Wm[(32 + k) * 32 + c];
        }
    }
    int c8 = lane & 7;
    const float* W = (lane < 8) ? W0 : W1;
    const float* a = (lane < 8) ? a0 : a1;
    float wv = 0.f;
#pragma unroll
    for (int k = 0; k < 32; k++) {
        float xk = __shfl_sync(FULL, x, k);
        wv += xk * W[k * 8 + c8];
    }
    if (lane < 16) g_Wh01[i * 16 + lane] = wv;
    float ts = wv * a[c8];
    float td = wv * a[8 + c8];
#pragma unroll
    for (int o = 4; o; o >>= 1) {
        ts += __shfl_xor_sync(FULL, ts, o);
        td += __shfl_xor_sync(FULL, td, o);
    }
    float fs1v = __shfl_sync(FULL, ts, 8);
    float fd1v = __shfl_sync(FULL, td, 8);
    if (lane == 0) {
        g_fs01[i] = make_float2(ts, fs1v);
        g_fd01[i] = make_float2(td, fd1v);
    }
}

// ============ kernel 2: fused CSR build + hidden attention + W_out map =======
// warp per row. Phase A: 4+4 double-buffered float4 stream (8 lines in flight
// per warp). __launch_bounds__(256,4) forces >=4 blocks/SM (32KB in flight/SM).
// Phase B: 2-head sparse softmax + gather + ELU + fused output-head linear.
__global__ void __launch_bounds__(256, 4) k_csr_attn(
    const float* __restrict__ adj, const float* __restrict__ Wo,
    const float* __restrict__ ao, int N)
{
    __shared__ int    nb_s[8][MAX_DEG];
    __shared__ float4 pack[8][MAX_DEG];
    int w = (blockIdx.x * blockDim.x + threadIdx.x) >> 5;
    int wl = threadIdx.x >> 5;
    int lane = threadIdx.x & 31;
    if (w >= N) return;

    // ---- Phase A: stream + compact ----
    const float4* row = reinterpret_cast<const float4*>(adj + (size_t)w * N);
    int n4 = N >> 2;
    int base = 0;
    float4 cur[4], nxt[4];
#pragma unroll
    for (int k = 0; k < 4; k++) {
        int idx = k * 32 + lane;
        cur[k] = make_float4(0.f, 0.f, 0.f, 0.f);
        if (idx < n4) cur[k] = __ldcs(row + idx);
    }
    for (int start = 0; start < n4; start += 128) {
        // prefetch next 4 chunks (independent; 8 lines in flight per warp)
#pragma unroll
        for (int k = 0; k < 4; k++) {
            int idx = start + 128 + k * 32 + lane;
            nxt[k] = make_float4(0.f, 0.f, 0.f, 0.f);
            if (idx < n4) nxt[k] = __ldcs(row + idx);
        }
        int fl[16];
#pragma unroll
        for (int k = 0; k < 4; k++) {
            fl[k * 4 + 0] = cur[k].x > 0.f;
            fl[k * 4 + 1] = cur[k].y > 0.f;
            fl[k * 4 + 2] = cur[k].z > 0.f;
            fl[k * 4 + 3] = cur[k].w > 0.f;
        }
        int cnt = 0;
#pragma unroll
        for (int e = 0; e < 16; e++) cnt += fl[e];
        int s = cnt;
#pragma unroll
        for (int off = 1; off < 32; off <<= 1) {
            int u = __shfl_up_sync(FULL, s, off);
            if (lane >= off) s += u;
        }
        int pos = base + (s - cnt);
#pragma unroll
        for (int k = 0; k < 4; k++) {
            int cb = (start + k * 32 + lane) * 4;
#pragma unroll
            for (int e = 0; e < 4; e++) {
                if (fl[k * 4 + e]) {
                    if (pos < MAX_DEG) nb_s[wl][pos] = cb + e;
                    pos++;
                }
            }
        }
        base += __shfl_sync(FULL, s, 31);
#pragma unroll
        for (int k = 0; k < 4; k++) cur[k] = nxt[k];
    }
    int rem = N & 3;
    if (rem) {
        int colbase = N & ~3;
        int flag = 0;
        if (lane < rem) flag = adj[(size_t)w * N + colbase + lane] > 0.f;
        int s = flag;
#pragma unroll
        for (int off = 1; off < 32; off <<= 1) {
            int u = __shfl_up_sync(FULL, s, off);
            if (lane >= off) s += u;
        }
        if (flag) {
            int pos = base + s - 1;
            if (pos < MAX_DEG) nb_s[wl][pos] = colbase + lane;
        }
        base += __shfl_sync(FULL, s, 31);
    }
    int deg = base < MAX_DEG ? base : MAX_DEG;
    __syncwarp();
    if (lane < deg) g_nbr[(size_t)w * MAX_DEG + lane] = nb_s[wl][lane];
    if (lane + 32 < deg) g_nbr[(size_t)w * MAX_DEG + lane + 32] = nb_s[wl][lane + 32];
    if (lane == 0) g_deg[w] = deg;

    // ---- Phase B: hidden 2-head attention ----
    float2 fsi = g_fs01[w];
    int j1 = (lane < deg) ? nb_s[wl][lane] : -1;
    int j2 = (lane + 32 < deg) ? nb_s[wl][lane + 32] : -1;
    float w01 = 0.f, w02 = 0.f, w11 = 0.f, w12 = 0.f;
    if (j1 >= 0) {
        float2 fd = g_fd01[j1];
        float a = fsi.x + fd.x; a = (a > 0.f) ? a : 0.2f * a; w01 = __expf(a);
        float b = fsi.y + fd.y; b = (b > 0.f) ? b : 0.2f * b; w11 = __expf(b);
    }
    if (j2 >= 0) {
        float2 fd = g_fd01[j2];
        float a = fsi.x + fd.x; a = (a > 0.f) ? a : 0.2f * a; w02 = __expf(a);
        float b = fsi.y + fd.y; b = (b > 0.f) ? b : 0.2f * b; w12 = __expf(b);
    }
    float s0 = w01 + w02, s1 = w11 + w12;
#pragma unroll
    for (int o = 16; o; o >>= 1) {
        s0 += __shfl_xor_sync(FULL, s0, o);
        s1 += __shfl_xor_sync(FULL, s1, o);
    }
    float inv0 = 1.f / s0, inv1 = 1.f / s1;
    pack[wl][lane]      = make_float4(__int_as_float(j1), w01 * inv0, w11 * inv1, 0.f);
    pack[wl][lane + 32] = make_float4(__int_as_float(j2), w02 * inv0, w12 * inv1, 0.f);
    __syncwarp();
    int half = lane >> 4, c = lane & 15;
    float acc = 0.f, acc2 = 0.f;
    int n = half;
    for (; n + 2 < deg; n += 4) {
        float4 va = pack[wl][n];
        float4 vb = pack[wl][n + 2];
        int ja = __float_as_int(va.x);
        int jb = __float_as_int(vb.x);
        acc  += ((c < 8) ? va.y : va.z) * g_Wh01[ja * 16 + c];
        acc2 += ((c < 8) ? vb.y : vb.z) * g_Wh01[jb * 16 + c];
    }
    for (; n < deg; n += 2) {
        float4 va = pack[wl][n];
        int ja = __float_as_int(va.x);
        acc += ((c < 8) ? va.y : va.z) * g_Wh01[ja * 16 + c];
    }
    acc += acc2;
    acc += __shfl_xor_sync(FULL, acc, 16);
    float h = (acc > 0.f) ? acc : (expf(acc) - 1.f);   // ELU on concat heads
    float who = 0.f;
#pragma unroll
    for (int k = 0; k < 16; k++) {
        float hk = __shfl_sync(FULL, h, k);
        who += hk * Wo[k * 16 + c];
    }
    float fs = who * ao[c];
    float fd = who * ao[16 + c];
#pragma unroll
    for (int o = 8; o; o >>= 1) {
        fs += __shfl_xor_sync(FULL, fs, o);
        fd += __shfl_xor_sync(FULL, fd, o);
    }
    if (half == 0) g_Who[w * 16 + c] = who;
    if (lane == 0) { g_fso[w] = fs; g_fdo[w] = fd; }
}

// ============ kernel 3: output attention head ============
__global__ void k_attn_out(int N)
{
    __shared__ float2 sm[8][MAX_DEG];
    int w = (blockIdx.x * blockDim.x + threadIdx.x) >> 5;
    int wl = threadIdx.x >> 5;
    int lane = threadIdx.x & 31;
    if (w >= N) return;
    int deg = g_deg[w];
    const int* nb = g_nbr + (size_t)w * MAX_DEG;
    int j1 = (lane < deg) ? nb[lane] : -1;
    int j2 = (lane + 32 < deg) ? nb[lane + 32] : -1;
    float fsi = g_fso[w];
    float w1 = 0.f, w2 = 0.f;
    if (j1 >= 0) { float a = fsi + g_fdo[j1]; a = (a > 0.f) ? a : 0.2f * a; w1 = __expf(a); }
    if (j2 >= 0) { float a = fsi + g_fdo[j2]; a = (a > 0.f) ? a : 0.2f * a; w2 = __expf(a); }
    float s = w1 + w2;
#pragma unroll
    for (int o = 16; o; o >>= 1) s += __shfl_xor_sync(FULL, s, o);
    float inv = 1.f / s;
    sm[wl][lane]      = make_float2(__int_as_float(j1), w1 * inv);
    sm[wl][lane + 32] = make_float2(__int_as_float(j2), w2 * inv);
    __syncwarp();
    int half = lane >> 4, c = lane & 15;
    float a0 = 0.f, a1 = 0.f, a2 = 0.f, a3 = 0.f;
    int n = half;
    for (; n + 6 < deg; n += 8) {
        float2 v0 = sm[wl][n];
        float2 v1 = sm[wl][n + 2];
        float2 v2 = sm[wl][n + 4];
        float2 v3 = sm[wl][n + 6];
        a0 += v0.y * g_Who[__float_as_int(v0.x) * 16 + c];
        a1 += v1.y * g_Who[__float_as_int(v1.x) * 16 + c];
        a2 += v2.y * g_Who[__float_as_int(v2.x) * 16 + c];
        a3 += v3.y * g_Who[__float_as_int(v3.x) * 16 + c];
    }
    for (; n < deg; n += 2) {
        float2 v0 = sm[wl][n];
        a0 += v0.y * g_Who[__float_as_int(v0.x) * 16 + c];
    }
    float acc = (a0 + a1) + (a2 + a3);
    acc += __shfl_xor_sync(FULL, acc, 16);
    float g = (acc > 0.f) ? acc : (expf(acc) - 1.f);   // outer ELU
    if (half == 0) g_gcn[w * 16 + c] = g;
}

// ============ kernel 4: prediction head (4 lanes per sample, float4 loads) ====
__global__ void k_pred(const int* __restrict__ uid, const int* __restrict__ mid,
                       const float* __restrict__ Wp, const float* __restrict__ bp,
                       float* __restrict__ out, int B, int U, int write_rating)
{
    int t = blockIdx.x * blockDim.x + threadIdx.x;
    int b = t >> 2;
    int q = t & 3;
    if (b >= B) return;
    int node = (q < 2) ? uid[b] : (mid[b] + U);
    int off = (q & 1) * 2;
    const float4* r = reinterpret_cast<const float4*>(g_gcn + (size_t)node * 16);
    const float4* wp = reinterpret_cast<const float4*>(Wp) + q * 2;
    float4 x0 = r[off], x1 = r[off + 1];
    float4 w0 = wp[0], w1 = wp[1];
    float acc = x0.x * w0.x + x0.y * w0.y + x0.z * w0.z + x0.w * w0.w
              + x1.x * w1.x + x1.y * w1.y + x1.z * w1.z + x1.w * w1.w;
    acc += __shfl_xor_sync(FULL, acc, 1);
    acc += __shfl_xor_sync(FULL, acc, 2);
    if (q == 0) {
        float p = 5.f / (1.f + expf(-(acc + bp[0])));
        out[b] = p;
        if (write_rating) out[B + b] = ceilf(p);
    }
}

// ---------------- launch ----------------
extern "C" void kernel_launch(void* const* d_in, const int* in_sizes, int n_in,
                              void* d_out, int out_size)
{
    const int*   uid        = (const int*)d_in[0];
    const int*   mid        = (const int*)d_in[1];
    const int*   all_gender = (const int*)d_in[2];
    const int*   all_age    = (const int*)d_in[3];
    const int*   all_job    = (const int*)d_in[4];
    const int*   all_mtype  = (const int*)d_in[5];
    const float* adj        = (const float*)d_in[6];
    const float* E_uid      = (const float*)d_in[7];
    const float* E_gender   = (const float*)d_in[8];
    const float* E_age      = (const float*)d_in[9];
    const float* E_job      = (const float*)d_in[10];
    const float* E_mid      = (const float*)d_in[11];
    const float* E_mtype    = (const float*)d_in[12];
    const float* W_user_map = (const float*)d_in[13];
    const float* b_user_map = (const float*)d_in[14];
    const float* W_movie    = (const float*)d_in[15];
    const float* b_movie    = (const float*)d_in[16];
    const float* W_h0       = (const float*)d_in[17];
    const float* a_h0       = (const float*)d_in[18];
    const float* W_h1       = (const float*)d_in[19];
    const float* a_h1       = (const float*)d_in[20];
    const float* W_out      = (const float*)d_in[21];
    const float* a_out      = (const float*)d_in[22];
    const float* W_pred     = (const float*)d_in[23];
    const float* b_pred     = (const float*)d_in[24];

    int B = in_sizes[0];
    int U = in_sizes[2];
    int M = in_sizes[5] / 3;
    int N = U + M;
    float* out = (float*)d_out;
    int write_rating = (out_size >= 2 * B) ? 1 : 0;

    int tpw = N * 32;
    k_feat_wh<<<(tpw + 255) / 256, 256>>>(
        all_gender, all_age, all_job, all_mtype,
        E_uid, E_gender, E_age, E_job, E_mid, E_mtype,
        W_user_map, b_user_map, W_movie, b_movie,
        W_h0, a_h0, W_h1, a_h1, U, N);
    k_csr_attn<<<(tpw + 255) / 256, 256>>>(adj, W_out, a_out, N);
    k_attn_out<<<(tpw + 255) / 256, 256>>>(N);
    k_pred<<<(B * 4 + 255) / 256, 256>>>(uid, mid, W_pred, b_pred, out, B, U, write_rating);
}

// round 16
// speedup vs baseline: 1.2050x; 1.0049x over previous
#include <cuda_runtime.h>

#define FULL 0xFFFFFFFFu
#define MAX_DEG 64
#define MAXN 10240

// ---------------- scratch (no allocations allowed) ----------------
__device__ int    g_nbr[MAXN * MAX_DEG];
__device__ int    g_deg[MAXN];
__device__ float  g_Wh01[MAXN * 16];     // cols 0-7 head0, 8-15 head1
__device__ float2 g_fs01[MAXN];          // (fs0, fs1)
__device__ float2 g_fd01[MAXN];          // (fd0, fd1)
__device__ float  g_Who[MAXN * 16];
__device__ float  g_fso[MAXN], g_fdo[MAXN];
__device__ float  g_gcn[MAXN * 16];

// ============ kernel 1: features + hidden-head Wh / attn coefficients ========
__global__ void k_feat_wh(
    const int* __restrict__ all_gender, const int* __restrict__ all_age,
    const int* __restrict__ all_job, const int* __restrict__ all_mtype,
    const float* __restrict__ E_uid, const float* __restrict__ E_gender,
    const float* __restrict__ E_age, const float* __restrict__ E_job,
    const float* __restrict__ E_mid, const float* __restrict__ E_mtype,
    const float* __restrict__ Wu, const float* __restrict__ bu,
    const float* __restrict__ Wm, const float* __restrict__ bm,
    const float* __restrict__ W0, const float* __restrict__ a0,
    const float* __restrict__ W1, const float* __restrict__ a1,
    int U, int N)
{
    int t = blockIdx.x * blockDim.x + threadIdx.x;
    int i = t >> 5;
    int lane = threadIdx.x & 31;
    if (i >= N) return;
    int c = lane;
    float x;
    if (i < U) {
        x = bu[c];
        const float* eu = E_uid + (size_t)i * 32;
#pragma unroll
        for (int k = 0; k < 32; k++) x += eu[k] * Wu[k * 32 + c];
        const float* eg = E_gender + all_gender[i] * 16;
#pragma unroll
        for (int k = 0; k < 16; k++) x += eg[k] * Wu[(32 + k) * 32 + c];
        const float* ea = E_age + all_age[i] * 16;
#pragma unroll
        for (int k = 0; k < 16; k++) x += ea[k] * Wu[(48 + k) * 32 + c];
        const float* ej = E_job + all_job[i] * 16;
#pragma unroll
        for (int k = 0; k < 16; k++) x += ej[k] * Wu[(64 + k) * 32 + c];
    } else {
        int m = i - U;
        x = bm[c];
        const float* em = E_mid + (size_t)m * 32;
#pragma unroll
        for (int k = 0; k < 32; k++) x += em[k] * Wm[k * 32 + c];
        int t0 = all_mtype[m * 3 + 0];
        int t1 = all_mtype[m * 3 + 1];
        int t2 = all_mtype[m * 3 + 2];
        const float* e0 = E_mtype + t0 * 32;
        const float* e1 = E_mtype + t1 * 32;
        const float* e2 = E_mtype + t2 * 32;
#pragma unroll
        for (int k = 0; k < 32; k++) {
            float s = e0[k] + e1[k] + e2[k];
            x += s * Wm[(32 + k) * 32 + c];
        }
    }
    int c8 = lane & 7;
    const float* W = (lane < 8) ? W0 : W1;
    const float* a = (lane < 8) ? a0 : a1;
    float wv = 0.f;
#pragma unroll
    for (int k = 0; k < 32; k++) {
        float xk = __shfl_sync(FULL, x, k);
        wv += xk * W[k * 8 + c8];
    }
    if (lane < 16) g_Wh01[i * 16 + lane] = wv;
    float ts = wv * a[c8];
    float td = wv * a[8 + c8];
#pragma unroll
    for (int o = 4; o; o >>= 1) {
        ts += __shfl_xor_sync(FULL, ts, o);
        td += __shfl_xor_sync(FULL, td, o);
    }
    float fs1v = __shfl_sync(FULL, ts, 8);
    float fd1v = __shfl_sync(FULL, td, 8);
    if (lane == 0) {
        g_fs01[i] = make_float2(ts, fs1v);
        g_fd01[i] = make_float2(td, fd1v);
    }
}

// ============ kernel 2: fused CSR build + hidden attention + W_out map =======
// warp per row. Phase A: 6+6 double-buffered float4 stream (12 lines in flight
// per warp = 1.5KB; ~36KB/SM at 3 blocks). Phase B: 2-head sparse softmax +
// gather + ELU + fused output-head linear.
__global__ void __launch_bounds__(256) k_csr_attn(
    const float* __restrict__ adj, const float* __restrict__ Wo,
    const float* __restrict__ ao, int N)
{
    __shared__ int    nb_s[8][MAX_DEG];
    __shared__ float4 pack[8][MAX_DEG];
    int w = (blockIdx.x * blockDim.x + threadIdx.x) >> 5;
    int wl = threadIdx.x >> 5;
    int lane = threadIdx.x & 31;
    if (w >= N) return;

    // ---- Phase A: stream + compact ----
    const float4* row = reinterpret_cast<const float4*>(adj + (size_t)w * N);
    int n4 = N >> 2;
    int base = 0;
    float4 cur[6], nxt[6];
#pragma unroll
    for (int k = 0; k < 6; k++) {
        int idx = k * 32 + lane;
        cur[k] = make_float4(0.f, 0.f, 0.f, 0.f);
        if (idx < n4) cur[k] = __ldcs(row + idx);
    }
    for (int start = 0; start < n4; start += 192) {
        // prefetch next 6 chunks (independent; 12 lines in flight per warp)
#pragma unroll
        for (int k = 0; k < 6; k++) {
            int idx = start + 192 + k * 32 + lane;
            nxt[k] = make_float4(0.f, 0.f, 0.f, 0.f);
            if (idx < n4) nxt[k] = __ldcs(row + idx);
        }
        int fl[24];
#pragma unroll
        for (int k = 0; k < 6; k++) {
            fl[k * 4 + 0] = cur[k].x > 0.f;
            fl[k * 4 + 1] = cur[k].y > 0.f;
            fl[k * 4 + 2] = cur[k].z > 0.f;
            fl[k * 4 + 3] = cur[k].w > 0.f;
        }
        int cnt = 0;
#pragma unroll
        for (int e = 0; e < 24; e++) cnt += fl[e];
        int s = cnt;
#pragma unroll
        for (int off = 1; off < 32; off <<= 1) {
            int u = __shfl_up_sync(FULL, s, off);
            if (lane >= off) s += u;
        }
        int pos = base + (s - cnt);
#pragma unroll
        for (int k = 0; k < 6; k++) {
            int cb = (start + k * 32 + lane) * 4;
#pragma unroll
            for (int e = 0; e < 4; e++) {
                if (fl[k * 4 + e]) {
                    if (pos < MAX_DEG) nb_s[wl][pos] = cb + e;
                    pos++;
                }
            }
        }
        base += __shfl_sync(FULL, s, 31);
#pragma unroll
        for (int k = 0; k < 6; k++) cur[k] = nxt[k];
    }
    int rem = N & 3;
    if (rem) {
        int colbase = N & ~3;
        int flag = 0;
        if (lane < rem) flag = adj[(size_t)w * N + colbase + lane] > 0.f;
        int s = flag;
#pragma unroll
        for (int off = 1; off < 32; off <<= 1) {
            int u = __shfl_up_sync(FULL, s, off);
            if (lane >= off) s += u;
        }
        if (flag) {
            int pos = base + s - 1;
            if (pos < MAX_DEG) nb_s[wl][pos] = colbase + lane;
        }
        base += __shfl_sync(FULL, s, 31);
    }
    int deg = base < MAX_DEG ? base : MAX_DEG;
    __syncwarp();
    if (lane < deg) g_nbr[(size_t)w * MAX_DEG + lane] = nb_s[wl][lane];
    if (lane + 32 < deg) g_nbr[(size_t)w * MAX_DEG + lane + 32] = nb_s[wl][lane + 32];
    if (lane == 0) g_deg[w] = deg;

    // ---- Phase B: hidden 2-head attention ----
    float2 fsi = g_fs01[w];
    int j1 = (lane < deg) ? nb_s[wl][lane] : -1;
    int j2 = (lane + 32 < deg) ? nb_s[wl][lane + 32] : -1;
    float w01 = 0.f, w02 = 0.f, w11 = 0.f, w12 = 0.f;
    if (j1 >= 0) {
        float2 fd = g_fd01[j1];
        float a = fsi.x + fd.x; a = (a > 0.f) ? a : 0.2f * a; w01 = __expf(a);
        float b = fsi.y + fd.y; b = (b > 0.f) ? b : 0.2f * b; w11 = __expf(b);
    }
    if (j2 >= 0) {
        float2 fd = g_fd01[j2];
        float a = fsi.x + fd.x; a = (a > 0.f) ? a : 0.2f * a; w02 = __expf(a);
        float b = fsi.y + fd.y; b = (b > 0.f) ? b : 0.2f * b; w12 = __expf(b);
    }
    float s0 = w01 + w02, s1 = w11 + w12;
#pragma unroll
    for (int o = 16; o; o >>= 1) {
        s0 += __shfl_xor_sync(FULL, s0, o);
        s1 += __shfl_xor_sync(FULL, s1, o);
    }
    float inv0 = 1.f / s0, inv1 = 1.f / s1;
    pack[wl][lane]      = make_float4(__int_as_float(j1), w01 * inv0, w11 * inv1, 0.f);
    pack[wl][lane + 32] = make_float4(__int_as_float(j2), w02 * inv0, w12 * inv1, 0.f);
    __syncwarp();
    int half = lane >> 4, c = lane & 15;
    float acc = 0.f, acc2 = 0.f;
    int n = half;
    for (; n + 2 < deg; n += 4) {
        float4 va = pack[wl][n];
        float4 vb = pack[wl][n + 2];
        int ja = __float_as_int(va.x);
        int jb = __float_as_int(vb.x);
        acc  += ((c < 8) ? va.y : va.z) * g_Wh01[ja * 16 + c];
        acc2 += ((c < 8) ? vb.y : vb.z) * g_Wh01[jb * 16 + c];
    }
    for (; n < deg; n += 2) {
        float4 va = pack[wl][n];
        int ja = __float_as_int(va.x);
        acc += ((c < 8) ? va.y : va.z) * g_Wh01[ja * 16 + c];
    }
    acc += acc2;
    acc += __shfl_xor_sync(FULL, acc, 16);
    float h = (acc > 0.f) ? acc : (expf(acc) - 1.f);   // ELU on concat heads
    float who = 0.f;
#pragma unroll
    for (int k = 0; k < 16; k++) {
        float hk = __shfl_sync(FULL, h, k);
        who += hk * Wo[k * 16 + c];
    }
    float fs = who * ao[c];
    float fd = who * ao[16 + c];
#pragma unroll
    for (int o = 8; o; o >>= 1) {
        fs += __shfl_xor_sync(FULL, fs, o);
        fd += __shfl_xor_sync(FULL, fd, o);
    }
    if (half == 0) g_Who[w * 16 + c] = who;
    if (lane == 0) { g_fso[w] = fs; g_fdo[w] = fd; }
}

// ============ kernel 3: output attention head ============
__global__ void k_attn_out(int N)
{
    __shared__ float2 sm[8][MAX_DEG];
    int w = (blockIdx.x * blockDim.x + threadIdx.x) >> 5;
    int wl = threadIdx.x >> 5;
    int lane = threadIdx.x & 31;
    if (w >= N) return;
    int deg = g_deg[w];
    const int* nb = g_nbr + (size_t)w * MAX_DEG;
    int j1 = (lane < deg) ? nb[lane] : -1;
    int j2 = (lane + 32 < deg) ? nb[lane + 32] : -1;
    float fsi = g_fso[w];
    float w1 = 0.f, w2 = 0.f;
    if (j1 >= 0) { float a = fsi + g_fdo[j1]; a = (a > 0.f) ? a : 0.2f * a; w1 = __expf(a); }
    if (j2 >= 0) { float a = fsi + g_fdo[j2]; a = (a > 0.f) ? a : 0.2f * a; w2 = __expf(a); }
    float s = w1 + w2;
#pragma unroll
    for (int o = 16; o; o >>= 1) s += __shfl_xor_sync(FULL, s, o);
    float inv = 1.f / s;
    sm[wl][lane]      = make_float2(__int_as_float(j1), w1 * inv);
    sm[wl][lane + 32] = make_float2(__int_as_float(j2), w2 * inv);
    __syncwarp();
    int half = lane >> 4, c = lane & 15;
    float a0 = 0.f, a1 = 0.f, a2 = 0.f, a3 = 0.f;
    int n = half;
    for (; n + 6 < deg; n += 8) {
        float2 v0 = sm[wl][n];
        float2 v1 = sm[wl][n + 2];
        float2 v2 = sm[wl][n + 4];
        float2 v3 = sm[wl][n + 6];
        a0 += v0.y * g_Who[__float_as_int(v0.x) * 16 + c];
        a1 += v1.y * g_Who[__float_as_int(v1.x) * 16 + c];
        a2 += v2.y * g_Who[__float_as_int(v2.x) * 16 + c];
        a3 += v3.y * g_Who[__float_as_int(v3.x) * 16 + c];
    }
    for (; n < deg; n += 2) {
        float2 v0 = sm[wl][n];
        a0 += v0.y * g_Who[__float_as_int(v0.x) * 16 + c];
    }
    float acc = (a0 + a1) + (a2 + a3);
    acc += __shfl_xor_sync(FULL, acc, 16);
    float g = (acc > 0.f) ? acc : (expf(acc) - 1.f);   // outer ELU
    if (half == 0) g_gcn[w * 16 + c] = g;
}

// ============ kernel 4: prediction head (4 lanes per sample, float4 loads) ====
__global__ void k_pred(const int* __restrict__ uid, const int* __restrict__ mid,
                       const float* __restrict__ Wp, const float* __restrict__ bp,
                       float* __restrict__ out, int B, int U, int write_rating)
{
    int t = blockIdx.x * blockDim.x + threadIdx.x;
    int b = t >> 2;
    int q = t & 3;
    if (b >= B) return;
    int node = (q < 2) ? uid[b] : (mid[b] + U);
    int off = (q & 1) * 2;
    const float4* r = reinterpret_cast<const float4*>(g_gcn + (size_t)node * 16);
    const float4* wp = reinterpret_cast<const float4*>(Wp) + q * 2;
    float4 x0 = r[off], x1 = r[off + 1];
    float4 w0 = wp[0], w1 = wp[1];
    float acc = x0.x * w0.x + x0.y * w0.y + x0.z * w0.z + x0.w * w0.w
              + x1.x * w1.x + x1.y * w1.y + x1.z * w1.z + x1.w * w1.w;
    acc += __shfl_xor_sync(FULL, acc, 1);
    acc += __shfl_xor_sync(FULL, acc, 2);
    if (q == 0) {
        float p = 5.f / (1.f + expf(-(acc + bp[0])));
        out[b] = p;
        if (write_rating) out[B + b] = ceilf(p);
    }
}

// ---------------- launch ----------------
extern "C" void kernel_launch(void* const* d_in, const int* in_sizes, int n_in,
                              void* d_out, int out_size)
{
    const int*   uid        = (const int*)d_in[0];
    const int*   mid        = (const int*)d_in[1];
    const int*   all_gender = (const int*)d_in[2];
    const int*   all_age    = (const int*)d_in[3];
    const int*   all_job    = (const int*)d_in[4];
    const int*   all_mtype  = (const int*)d_in[5];
    const float* adj        = (const float*)d_in[6];
    const float* E_uid      = (const float*)d_in[7];
    const float* E_gender   = (const float*)d_in[8];
    const float* E_age      = (const float*)d_in[9];
    const float* E_job      = (const float*)d_in[10];
    const float* E_mid      = (const float*)d_in[11];
    const float* E_mtype    = (const float*)d_in[12];
    const float* W_user_map = (const float*)d_in[13];
    const float* b_user_map = (const float*)d_in[14];
    const float* W_movie    = (const float*)d_in[15];
    const float* b_movie    = (const float*)d_in[16];
    const float* W_h0       = (const float*)d_in[17];
    const float* a_h0       = (const float*)d_in[18];
    const float* W_h1       = (const float*)d_in[19];
    const float* a_h1       = (const float*)d_in[20];
    const float* W_out      = (const float*)d_in[21];
    const float* a_out      = (const float*)d_in[22];
    const float* W_pred     = (const float*)d_in[23];
    const float* b_pred     = (const float*)d_in[24];

    int B = in_sizes[0];
    int U = in_sizes[2];
    int M = in_sizes[5] / 3;
    int N = U + M;
    float* out = (float*)d_out;
    int write_rating = (out_size >= 2 * B) ? 1 : 0;

    int tpw = N * 32;
    k_feat_wh<<<(tpw + 255) / 256, 256>>>(
        all_gender, all_age, all_job, all_mtype,
        E_uid, E_gender, E_age, E_job, E_mid, E_mtype,
        W_user_map, b_user_map, W_movie, b_movie,
        W_h0, a_h0, W_h1, a_h1, U, N);
    k_csr_attn<<<(tpw + 255) / 256, 256>>>(adj, W_out, a_out, N);
    k_attn_out<<<(tpw + 255) / 256, 256>>>(N);
    k_pred<<<(B * 4 + 255) / 256, 256>>>(uid, mid, W_pred, b_pred, out, B, U, write_rating);
}

// round 17
// speedup vs baseline: 1.3312x; 1.1047x over previous
#include <cuda_runtime.h>

#define FULL 0xFFFFFFFFu
#define MAX_DEG 64
#define MAXN 10240

// ---------------- scratch (no allocations allowed) ----------------
__device__ int    g_nbr[MAXN * MAX_DEG];
__device__ int    g_deg[MAXN];
__device__ float  g_Wh01[MAXN * 16];     // cols 0-7 head0, 8-15 head1
__device__ float2 g_fs01[MAXN];          // (fs0, fs1)
__device__ float2 g_fd01[MAXN];          // (fd0, fd1)
__device__ float  g_Who[MAXN * 16];
__device__ float  g_fso[MAXN], g_fdo[MAXN];
__device__ float  g_gcn[MAXN * 16];

// ============ kernel 1: features + hidden-head Wh / attn coefficients ========
__global__ void k_feat_wh(
    const int* __restrict__ all_gender, const int* __restrict__ all_age,
    const int* __restrict__ all_job, const int* __restrict__ all_mtype,
    const float* __restrict__ E_uid, const float* __restrict__ E_gender,
    const float* __restrict__ E_age, const float* __restrict__ E_job,
    const float* __restrict__ E_mid, const float* __restrict__ E_mtype,
    const float* __restrict__ Wu, const float* __restrict__ bu,
    const float* __restrict__ Wm, const float* __restrict__ bm,
    const float* __restrict__ W0, const float* __restrict__ a0,
    const float* __restrict__ W1, const float* __restrict__ a1,
    int U, int N)
{
    int t = blockIdx.x * blockDim.x + threadIdx.x;
    int i = t >> 5;
    int lane = threadIdx.x & 31;
    if (i >= N) return;
    int c = lane;
    float x;
    if (i < U) {
        x = bu[c];
        const float* eu = E_uid + (size_t)i * 32;
#pragma unroll
        for (int k = 0; k < 32; k++) x += eu[k] * Wu[k * 32 + c];
        const float* eg = E_gender + all_gender[i] * 16;
#pragma unroll
        for (int k = 0; k < 16; k++) x += eg[k] * Wu[(32 + k) * 32 + c];
        const float* ea = E_age + all_age[i] * 16;
#pragma unroll
        for (int k = 0; k < 16; k++) x += ea[k] * Wu[(48 + k) * 32 + c];
        const float* ej = E_job + all_job[i] * 16;
#pragma unroll
        for (int k = 0; k < 16; k++) x += ej[k] * Wu[(64 + k) * 32 + c];
    } else {
        int m = i - U;
        x = bm[c];
        const float* em = E_mid + (size_t)m * 32;
#pragma unroll
        for (int k = 0; k < 32; k++) x += em[k] * Wm[k * 32 + c];
        int t0 = all_mtype[m * 3 + 0];
        int t1 = all_mtype[m * 3 + 1];
        int t2 = all_mtype[m * 3 + 2];
        const float* e0 = E_mtype + t0 * 32;
        const float* e1 = E_mtype + t1 * 32;
        const float* e2 = E_mtype + t2 * 32;
#pragma unroll
        for (int k = 0; k < 32; k++) {
            float s = e0[k] + e1[k] + e2[k];
            x += s * Wm[(32 + k) * 32 + c];
        }
    }
    int c8 = lane & 7;
    const float* W = (lane < 8) ? W0 : W1;
    const float* a = (lane < 8) ? a0 : a1;
    float wv = 0.f;
#pragma unroll
    for (int k = 0; k < 32; k++) {
        float xk = __shfl_sync(FULL, x, k);
        wv += xk * W[k * 8 + c8];
    }
    if (lane < 16) g_Wh01[i * 16 + lane] = wv;
    float ts = wv * a[c8];
    float td = wv * a[8 + c8];
#pragma unroll
    for (int o = 4; o; o >>= 1) {
        ts += __shfl_xor_sync(FULL, ts, o);
        td += __shfl_xor_sync(FULL, td, o);
    }
    float fs1v = __shfl_sync(FULL, ts, 8);
    float fd1v = __shfl_sync(FULL, td, 8);
    if (lane == 0) {
        g_fs01[i] = make_float2(ts, fs1v);
        g_fd01[i] = make_float2(td, fd1v);
    }
}

// ============ kernel 2: fused CSR build + hidden attention + W_out map =======
// warp per row, 128-thread blocks (4 warps) for finer register-file residency
// quantization (7 blocks/SM = 28 warps vs 24 at 256 threads). Phase A: 4+4
// double-buffered float4 stream. Phase B: 2-head sparse softmax + gather +
// ELU + fused output-head linear. Logic identical to the proven R4 kernel.
__global__ void __launch_bounds__(128) k_csr_attn(
    const float* __restrict__ adj, const float* __restrict__ Wo,
    const float* __restrict__ ao, int N)
{
    __shared__ int    nb_s[4][MAX_DEG];
    __shared__ float4 pack[4][MAX_DEG];
    int w = (blockIdx.x * blockDim.x + threadIdx.x) >> 5;
    int wl = threadIdx.x >> 5;
    int lane = threadIdx.x & 31;
    if (w >= N) return;

    // ---- Phase A: stream + compact ----
    const float4* row = reinterpret_cast<const float4*>(adj + (size_t)w * N);
    int n4 = N >> 2;
    int base = 0;
    float4 cur[4], nxt[4];
#pragma unroll
    for (int k = 0; k < 4; k++) {
        int idx = k * 32 + lane;
        cur[k] = make_float4(0.f, 0.f, 0.f, 0.f);
        if (idx < n4) cur[k] = __ldcs(row + idx);
    }
    for (int start = 0; start < n4; start += 128) {
        // prefetch next 4 chunks (independent; 8 lines in flight per warp)
#pragma unroll
        for (int k = 0; k < 4; k++) {
            int idx = start + 128 + k * 32 + lane;
            nxt[k] = make_float4(0.f, 0.f, 0.f, 0.f);
            if (idx < n4) nxt[k] = __ldcs(row + idx);
        }
        int fl[16];
#pragma unroll
        for (int k = 0; k < 4; k++) {
            fl[k * 4 + 0] = cur[k].x > 0.f;
            fl[k * 4 + 1] = cur[k].y > 0.f;
            fl[k * 4 + 2] = cur[k].z > 0.f;
            fl[k * 4 + 3] = cur[k].w > 0.f;
        }
        int cnt = 0;
#pragma unroll
        for (int e = 0; e < 16; e++) cnt += fl[e];
        int s = cnt;
#pragma unroll
        for (int off = 1; off < 32; off <<= 1) {
            int u = __shfl_up_sync(FULL, s, off);
            if (lane >= off) s += u;
        }
        int pos = base + (s - cnt);
#pragma unroll
        for (int k = 0; k < 4; k++) {
            int cb = (start + k * 32 + lane) * 4;
#pragma unroll
            for (int e = 0; e < 4; e++) {
                if (fl[k * 4 + e]) {
                    if (pos < MAX_DEG) nb_s[wl][pos] = cb + e;
                    pos++;
                }
            }
        }
        base += __shfl_sync(FULL, s, 31);
#pragma unroll
        for (int k = 0; k < 4; k++) cur[k] = nxt[k];
    }
    int rem = N & 3;
    if (rem) {
        int colbase = N & ~3;
        int flag = 0;
        if (lane < rem) flag = adj[(size_t)w * N + colbase + lane] > 0.f;
        int s = flag;
#pragma unroll
        for (int off = 1; off < 32; off <<= 1) {
            int u = __shfl_up_sync(FULL, s, off);
            if (lane >= off) s += u;
        }
        if (flag) {
            int pos = base + s - 1;
            if (pos < MAX_DEG) nb_s[wl][pos] = colbase + lane;
        }
        base += __shfl_sync(FULL, s, 31);
    }
    int deg = base < MAX_DEG ? base : MAX_DEG;
    __syncwarp();
    if (lane < deg) g_nbr[(size_t)w * MAX_DEG + lane] = nb_s[wl][lane];
    if (lane + 32 < deg) g_nbr[(size_t)w * MAX_DEG + lane + 32] = nb_s[wl][lane + 32];
    if (lane == 0) g_deg[w] = deg;

    // ---- Phase B: hidden 2-head attention ----
    float2 fsi = g_fs01[w];
    int j1 = (lane < deg) ? nb_s[wl][lane] : -1;
    int j2 = (lane + 32 < deg) ? nb_s[wl][lane + 32] : -1;
    float w01 = 0.f, w02 = 0.f, w11 = 0.f, w12 = 0.f;
    if (j1 >= 0) {
        float2 fd = g_fd01[j1];
        float a = fsi.x + fd.x; a = (a > 0.f) ? a : 0.2f * a; w01 = __expf(a);
        float b = fsi.y + fd.y; b = (b > 0.f) ? b : 0.2f * b; w11 = __expf(b);
    }
    if (j2 >= 0) {
        float2 fd = g_fd01[j2];
        float a = fsi.x + fd.x; a = (a > 0.f) ? a : 0.2f * a; w02 = __expf(a);
        float b = fsi.y + fd.y; b = (b > 0.f) ? b : 0.2f * b; w12 = __expf(b);
    }
    float s0 = w01 + w02, s1 = w11 + w12;
#pragma unroll
    for (int o = 16; o; o >>= 1) {
        s0 += __shfl_xor_sync(FULL, s0, o);
        s1 += __shfl_xor_sync(FULL, s1, o);
    }
    float inv0 = 1.f / s0, inv1 = 1.f / s1;
    pack[wl][lane]      = make_float4(__int_as_float(j1), w01 * inv0, w11 * inv1, 0.f);
    pack[wl][lane + 32] = make_float4(__int_as_float(j2), w02 * inv0, w12 * inv1, 0.f);
    __syncwarp();
    int half = lane >> 4, c = lane & 15;
    float acc = 0.f, acc2 = 0.f;
    int n = half;
    for (; n + 2 < deg; n += 4) {
        float4 va = pack[wl][n];
        float4 vb = pack[wl][n + 2];
        int ja = __float_as_int(va.x);
        int jb = __float_as_int(vb.x);
        acc  += ((c < 8) ? va.y : va.z) * g_Wh01[ja * 16 + c];
        acc2 += ((c < 8) ? vb.y : vb.z) * g_Wh01[jb * 16 + c];
    }
    for (; n < deg; n += 2) {
        float4 va = pack[wl][n];
        int ja = __float_as_int(va.x);
        acc += ((c < 8) ? va.y : va.z) * g_Wh01[ja * 16 + c];
    }
    acc += acc2;
    acc += __shfl_xor_sync(FULL, acc, 16);
    float h = (acc > 0.f) ? acc : (expf(acc) - 1.f);   // ELU on concat heads
    float who = 0.f;
#pragma unroll
    for (int k = 0; k < 16; k++) {
        float hk = __shfl_sync(FULL, h, k);
        who += hk * Wo[k * 16 + c];
    }
    float fs = who * ao[c];
    float fd = who * ao[16 + c];
#pragma unroll
    for (int o = 8; o; o >>= 1) {
        fs += __shfl_xor_sync(FULL, fs, o);
        fd += __shfl_xor_sync(FULL, fd, o);
    }
    if (half == 0) g_Who[w * 16 + c] = who;
    if (lane == 0) { g_fso[w] = fs; g_fdo[w] = fd; }
}

// ============ kernel 3: output attention head ============
__global__ void k_attn_out(int N)
{
    __shared__ float2 sm[8][MAX_DEG];
    int w = (blockIdx.x * blockDim.x + threadIdx.x) >> 5;
    int wl = threadIdx.x >> 5;
    int lane = threadIdx.x & 31;
    if (w >= N) return;
    int deg = g_deg[w];
    const int* nb = g_nbr + (size_t)w * MAX_DEG;
    int j1 = (lane < deg) ? nb[lane] : -1;
    int j2 = (lane + 32 < deg) ? nb[lane + 32] : -1;
    float fsi = g_fso[w];
    float w1 = 0.f, w2 = 0.f;
    if (j1 >= 0) { float a = fsi + g_fdo[j1]; a = (a > 0.f) ? a : 0.2f * a; w1 = __expf(a); }
    if (j2 >= 0) { float a = fsi + g_fdo[j2]; a = (a > 0.f) ? a : 0.2f * a; w2 = __expf(a); }
    float s = w1 + w2;
#pragma unroll
    for (int o = 16; o; o >>= 1) s += __shfl_xor_sync(FULL, s, o);
    float inv = 1.f / s;
    sm[wl][lane]      = make_float2(__int_as_float(j1), w1 * inv);
    sm[wl][lane + 32] = make_float2(__int_as_float(j2), w2 * inv);
    __syncwarp();
    int half = lane >> 4, c = lane & 15;
    float a0 = 0.f, a1 = 0.f, a2 = 0.f, a3 = 0.f;
    int n = half;
    for (; n + 6 < deg; n += 8) {
        float2 v0 = sm[wl][n];
        float2 v1 = sm[wl][n + 2];
        float2 v2 = sm[wl][n + 4];
        float2 v3 = sm[wl][n + 6];
        a0 += v0.y * g_Who[__float_as_int(v0.x) * 16 + c];
        a1 += v1.y * g_Who[__float_as_int(v1.x) * 16 + c];
        a2 += v2.y * g_Who[__float_as_int(v2.x) * 16 + c];
        a3 += v3.y * g_Who[__float_as_int(v3.x) * 16 + c];
    }
    for (; n < deg; n += 2) {
        float2 v0 = sm[wl][n];
        a0 += v0.y * g_Who[__float_as_int(v0.x) * 16 + c];
    }
    float acc = (a0 + a1) + (a2 + a3);
    acc += __shfl_xor_sync(FULL, acc, 16);
    float g = (acc > 0.f) ? acc : (expf(acc) - 1.f);   // outer ELU
    if (half == 0) g_gcn[w * 16 + c] = g;
}

// ============ kernel 4: prediction head (4 lanes per sample, float4 loads) ====
__global__ void k_pred(const int* __restrict__ uid, const int* __restrict__ mid,
                       const float* __restrict__ Wp, const float* __restrict__ bp,
                       float* __restrict__ out, int B, int U, int write_rating)
{
    int t = blockIdx.x * blockDim.x + threadIdx.x;
    int b = t >> 2;
    int q = t & 3;
    if (b >= B) return;
    int node = (q < 2) ? uid[b] : (mid[b] + U);
    int off = (q & 1) * 2;
    const float4* r = reinterpret_cast<const float4*>(g_gcn + (size_t)node * 16);
    const float4* wp = reinterpret_cast<const float4*>(Wp) + q * 2;
    float4 x0 = r[off], x1 = r[off + 1];
    float4 w0 = wp[0], w1 = wp[1];
    float acc = x0.x * w0.x + x0.y * w0.y + x0.z * w0.z + x0.w * w0.w
              + x1.x * w1.x + x1.y * w1.y + x1.z * w1.z + x1.w * w1.w;
    acc += __shfl_xor_sync(FULL, acc, 1);
    acc += __shfl_xor_sync(FULL, acc, 2);
    if (q == 0) {
        float p = 5.f / (1.f + expf(-(acc + bp[0])));
        out[b] = p;
        if (write_rating) out[B + b] = ceilf(p);
    }
}

// ---------------- launch ----------------
extern "C" void kernel_launch(void* const* d_in, const int* in_sizes, int n_in,
                              void* d_out, int out_size)
{
    const int*   uid        = (const int*)d_in[0];
    const int*   mid        = (const int*)d_in[1];
    const int*   all_gender = (const int*)d_in[2];
    const int*   all_age    = (const int*)d_in[3];
    const int*   all_job    = (const int*)d_in[4];
    const int*   all_mtype  = (const int*)d_in[5];
    const float* adj        = (const float*)d_in[6];
    const float* E_uid      = (const float*)d_in[7];
    const float* E_gender   = (const float*)d_in[8];
    const float* E_age      = (const float*)d_in[9];
    const float* E_job      = (const float*)d_in[10];
    const float* E_mid      = (const float*)d_in[11];
    const float* E_mtype    = (const float*)d_in[12];
    const float* W_user_map = (const float*)d_in[13];
    const float* b_user_map = (const float*)d_in[14];
    const float* W_movie    = (const float*)d_in[15];
    const float* b_movie    = (const float*)d_in[16];
    const float* W_h0       = (const float*)d_in[17];
    const float* a_h0       = (const float*)d_in[18];
    const float* W_h1       = (const float*)d_in[19];
    const float* a_h1       = (const float*)d_in[20];
    const float* W_out      = (const float*)d_in[21];
    const float* a_out      = (const float*)d_in[22];
    const float* W_pred     = (const float*)d_in[23];
    const float* b_pred     = (const float*)d_in[24];

    int B = in_sizes[0];
    int U = in_sizes[2];
    int M = in_sizes[5] / 3;
    int N = U + M;
    float* out = (float*)d_out;
    int write_rating = (out_size >= 2 * B) ? 1 : 0;

    int tpw = N * 32;
    k_feat_wh<<<(tpw + 255) / 256, 256>>>(
        all_gender, all_age, all_job, all_mtype,
        E_uid, E_gender, E_age, E_job, E_mid, E_mtype,
        W_user_map, b_user_map, W_movie, b_movie,
        W_h0, a_h0, W_h1, a_h1, U, N);
    k_csr_attn<<<(tpw + 127) / 128, 128>>>(adj, W_out, a_out, N);
    k_attn_out<<<(tpw + 255) / 256, 256>>>(N);
    k_pred<<<(B * 4 + 255) / 256, 256>>>(uid, mid, W_pred, b_pred, out, B, U, write_rating);
}